// round 9
// baseline (speedup 1.0000x reference)
#include <cuda_runtime.h>
#include <cuda_bf16.h>
#include <cstdint>

#define BDIM 8
#define NDIM 2048
#define FIN 16
#define FOUT 64
#define TDIM 12
#define CDIM 192
#define TM 32    // n-tile per CTA
#define MC 32    // m per chunk
#define ASTR 20  // packed A smem word stride
#define XSTR 20  // packed X smem word stride
#define CH 144   // columns on HMMA path
#define CF 48    // columns on FFMA path

// ---- device scratch (no cudaMalloc allowed) ----
__device__ float g_deg[NDIM];
__device__ float g_inv0[BDIM*NDIM];
__device__ uint32_t g_xTb[(size_t)BDIM*CDIM*(NDIM/2)];  // bf16x2 (x[m],x[m+1]) at [b][c][m/2]

__device__ __forceinline__ uint32_t pack2(float a, float b) {
    __nv_bfloat162 h = __floats2bfloat162_rn(a, b);
    return *(uint32_t*)&h;
}

// ---------------------------------------------------------------------------
// x[b][m][c] (f32) -> g_xTb[b][c][m/2] (bf16x2)
__global__ void xT_kernel(const float* __restrict__ x) {
    __shared__ float t[32][33];
    int b = blockIdx.z, c0 = blockIdx.y * 32, m0 = blockIdx.x * 32;
    int tx = threadIdx.x & 31, ty = threadIdx.x >> 5;
    #pragma unroll
    for (int j = 0; j < 4; j++)
        t[ty + j * 8][tx] = x[((size_t)b * NDIM + m0 + ty + j * 8) * CDIM + c0 + tx];
    __syncthreads();
    int q = threadIdx.x & 15;
    int cbase = threadIdx.x >> 4;
    #pragma unroll
    for (int j = 0; j < 2; j++) {
        int cc = cbase + 16 * j;
        uint32_t v = pack2(t[2 * q][cc], t[2 * q + 1][cc]);
        g_xTb[(((size_t)b * CDIM + c0 + cc) << 10) + (m0 >> 1) + q] = v;
    }
}

// ---------------------------------------------------------------------------
// prep: y<8 -> inv0[b=y,n];  y==8 -> deg rows
__global__ void prep_kernel(const float* __restrict__ sa, const float* __restrict__ adj) {
    if (blockIdx.y < 8) {
        int b = blockIdx.y;
        int n = blockIdx.x * 256 + threadIdx.x;
        const float* p = sa + (size_t)(b * 3) * NDIM * NDIM + n;
        float s0 = 0.f, s1 = 0.f, s2 = 0.f, s3 = 0.f;
        #pragma unroll 1
        for (int m = 0; m < NDIM; m += 4) {
            s0 += __expf(p[(size_t)(m + 0) * NDIM]);
            s1 += __expf(p[(size_t)(m + 1) * NDIM]);
            s2 += __expf(p[(size_t)(m + 2) * NDIM]);
            s3 += __expf(p[(size_t)(m + 3) * NDIM]);
        }
        g_inv0[b * NDIM + n] = 1.f / (s0 + s1 + s2 + s3);
    } else {
        int gw = blockIdx.x * 8 + (threadIdx.x >> 5);
        int lane = threadIdx.x & 31;
        for (int row = gw; row < NDIM; row += 64) {
            const float4* r = (const float4*)(adj + (size_t)row * NDIM);
            float s = 0.f;
            #pragma unroll
            for (int i = 0; i < 16; i++) {
                float4 v = r[lane + i * 32];
                s += v.x + v.y + v.z + v.w;
            }
            #pragma unroll
            for (int o = 16; o; o >>= 1) s += __shfl_xor_sync(0xffffffffu, s, o);
            if (lane == 0) g_deg[row] = s;
        }
    }
}

// ---------------------------------------------------------------------------
// Fused main kernel. Warps 0-3: bf16 HMMA on cols [0,144). Warps 4-7 (one per
// SMSP): fp32 FFMA on cols [144,192). Diagonal terms exact fp32 in epilogue.
__global__ __launch_bounds__(256, 2)
void main_kernel(const float* __restrict__ x,
                 const float* __restrict__ sa,
                 const float* __restrict__ adj,
                 const float* __restrict__ Theta,
                 float* __restrict__ out)
{
    __shared__ float smem[12288];                    // 48 KB, phase-overlaid
    uint32_t* A1w = (uint32_t*)smem;                 // [32 n][20 w] bf16x2
    uint32_t* A2w = A1w + TM * ASTR;                 // [32 n][20 w]
    uint32_t* Xw  = A2w + TM * ASTR;                 // [144 c][20 w]
    float* A32 = smem + 2 * TM * ASTR + CH * XSTR;   // [2 k][32 m][36 n] fp32
    float* X32 = A32 + 2 * 32 * 36;                  // [32 m][48 c] fp32
    // mainloop usage ends at word 8000 < 12288; epilogue overlays rhs [2][32][192]

    const int b    = blockIdx.y;
    const int n0   = blockIdx.x * TM;
    const int tid  = threadIdx.x;
    const int lane = tid & 31;
    const int wid  = tid >> 5;
    const int g    = lane >> 2;
    const int tig  = lane & 3;

    const float* sa1 = sa + (size_t)(b * 3 + 1) * NDIM * NDIM;
    const float* sa2 = sa + (size_t)(b * 3 + 2) * NDIM * NDIM;
    const float* xb  = x + (size_t)b * NDIM * CDIM;

    float acc[72];                         // HMMA: [2 rt][9 ct][4]; FFMA: first 24 = [4 n][6 c]
    #pragma unroll
    for (int i = 0; i < 72; i++) acc[i] = 0.f;

    float sum1 = 0.f, sum2 = 0.f;
    const int n_g = n0 + lane;
    const uint32_t* xsrc = &g_xTb[((size_t)b * CDIM) << 10];

    const int ksel = wid & 1;              // both paths: 0 -> k=1, 1 -> k=2
    const int cg0  = (wid >> 1) * 72;      // HMMA col group (wid 0-3)
    const int coff = ((wid >> 1) & 1) * 24 + (lane >> 3) * 6;   // FFMA col offset in X32
    const int nb   = lane & 7;             // FFMA n-quad

    for (int m0 = 0; m0 < NDIM; m0 += MC) {
        __syncthreads();
        // ---- build weight tiles (all warps): packed bf16 + fp32 copies ----
        #pragma unroll
        for (int i = 0; i < 2; i++) {
            int p = wid * 2 + i;           // m-pair 0..15
            int m = m0 + 2 * p;
            float a0 = adj[(size_t)m * NDIM + n_g];
            float a1 = adj[(size_t)(m + 1) * NDIM + n_g];
            float e10 = __expf(sa1[(size_t)m * NDIM + n_g]);
            float e11 = __expf(sa1[(size_t)(m + 1) * NDIM + n_g]);
            float e20 = __expf(sa2[(size_t)m * NDIM + n_g]);
            float e21 = __expf(sa2[(size_t)(m + 1) * NDIM + n_g]);
            sum1 += e10 + e11; sum2 += e20 + e21;
            bool d0 = (m == n_g), d1 = (m + 1 == n_g);
            float w10 = d0 ? 0.f : (-a0) * e10;
            float w11 = d1 ? 0.f : (-a1) * e11;
            float w20 = d0 ? 0.f : (2.f * a0 * a0) * e20;
            float w21 = d1 ? 0.f : (2.f * a1 * a1) * e21;
            A1w[lane * ASTR + p] = pack2(w10, w11);
            A2w[lane * ASTR + p] = pack2(w20, w21);
            A32[(2 * p) * 36 + lane]            = w10;
            A32[(2 * p + 1) * 36 + lane]        = w11;
            A32[1152 + (2 * p) * 36 + lane]     = w20;
            A32[1152 + (2 * p + 1) * 36 + lane] = w21;
        }
        // ---- packed X tile: cols [0,144) ----
        #pragma unroll
        for (int i = 0; i < 9; i++) {
            int e = tid + i * 256;         // 0..2303
            int c = e >> 4, q = e & 15;
            Xw[c * XSTR + q] = xsrc[((size_t)c << 10) + (m0 >> 1) + q];
        }
        // ---- fp32 X tile: cols [144,192) ----
        #pragma unroll
        for (int i = 0; i < 2; i++) {
            int e = tid + i * 256;
            if (e < 384) {
                int m = e / 12, q = e % 12;
                *(float4*)&X32[m * 48 + q * 4] =
                    *(const float4*)&xb[(size_t)(m0 + m) * CDIM + 144 + q * 4];
            }
        }
        __syncthreads();

        if (wid < 4) {
            // ---- bf16 m16n8k16 path: 72 cols per warp ----
            const uint32_t* Aw = ksel ? A2w : A1w;
            #pragma unroll
            for (int kk = 0; kk < 2; kk++) {
                uint32_t afr[2][4];
                #pragma unroll
                for (int rt = 0; rt < 2; rt++) {
                    int r0 = rt * 16 + g;
                    afr[rt][0] = Aw[r0 * ASTR + kk * 8 + tig];
                    afr[rt][1] = Aw[(r0 + 8) * ASTR + kk * 8 + tig];
                    afr[rt][2] = Aw[r0 * ASTR + kk * 8 + tig + 4];
                    afr[rt][3] = Aw[(r0 + 8) * ASTR + kk * 8 + tig + 4];
                }
                #pragma unroll
                for (int ct = 0; ct < 9; ct++) {
                    int c = cg0 + ct * 8 + g;
                    uint32_t b0 = Xw[c * XSTR + kk * 8 + tig];
                    uint32_t b1 = Xw[c * XSTR + kk * 8 + tig + 4];
                    #pragma unroll
                    for (int rt = 0; rt < 2; rt++) {
                        float* dd = &acc[(rt * 9 + ct) * 4];
                        asm volatile(
                            "mma.sync.aligned.m16n8k16.row.col.f32.bf16.bf16.f32 "
                            "{%0,%1,%2,%3}, {%4,%5,%6,%7}, {%8,%9}, {%0,%1,%2,%3};\n"
                            : "+f"(dd[0]), "+f"(dd[1]), "+f"(dd[2]), "+f"(dd[3])
                            : "r"(afr[rt][0]), "r"(afr[rt][1]), "r"(afr[rt][2]), "r"(afr[rt][3]),
                              "r"(b0), "r"(b1));
                    }
                }
            }
        } else {
            // ---- fp32 FFMA path: 24 cols per warp, 32 n ----
            const float* a32k = A32 + ksel * 1152;
            #pragma unroll 4
            for (int m = 0; m < 32; m++) {
                float4 wv = *(const float4*)&a32k[m * 36 + nb * 4];
                const float* xp = &X32[m * 48 + coff];
                float x0 = xp[0], x1 = xp[1], x2 = xp[2];
                float x3 = xp[3], x4 = xp[4], x5 = xp[5];
                #pragma unroll
                for (int i = 0; i < 4; i++) {
                    float w = (i == 0) ? wv.x : (i == 1) ? wv.y : (i == 2) ? wv.z : wv.w;
                    acc[i * 6 + 0] += w * x0;
                    acc[i * 6 + 1] += w * x1;
                    acc[i * 6 + 2] += w * x2;
                    acc[i * 6 + 3] += w * x3;
                    acc[i * 6 + 4] += w * x4;
                    acc[i * 6 + 5] += w * x5;
                }
            }
        }
    }

    // ---- reduce softmax denominators (8 partials per column) ----
    __syncthreads();
    smem[wid * 32 + lane]       = sum1;
    smem[256 + wid * 32 + lane] = sum2;
    __syncthreads();
    if (tid < 64) {
        int k = tid >> 5, nl = tid & 31;
        float s = 0.f;
        #pragma unroll
        for (int w = 0; w < 8; w++) s += smem[k * 256 + w * 32 + nl];
        smem[512 + k * 32 + nl] = 1.f / s;
    }
    __syncthreads();

    const int o    = tid & 63;
    const int ngrp = tid >> 6;
    float inv1r[8], inv2r[8];
    #pragma unroll
    for (int nn = 0; nn < 8; nn++) {
        int nl = ngrp * 8 + nn;
        inv1r[nn] = smem[512 + nl];
        inv2r[nn] = smem[512 + 32 + nl];
    }
    __syncthreads();

    // ---- spill accumulators to rhs smem [k][32 n][192 c] ----
    if (wid < 4) {
        #pragma unroll
        for (int rt = 0; rt < 2; rt++)
            #pragma unroll
            for (int ct = 0; ct < 9; ct++) {
                const float* dd = &acc[(rt * 9 + ct) * 4];
                int r0 = ksel * 32 + rt * 16 + g;
                int c  = cg0 + ct * 8 + 2 * tig;
                *(float2*)&smem[r0 * 192 + c]       = make_float2(dd[0], dd[1]);
                *(float2*)&smem[(r0 + 8) * 192 + c] = make_float2(dd[2], dd[3]);
            }
    } else {
        #pragma unroll
        for (int i = 0; i < 4; i++)
            #pragma unroll
            for (int jp = 0; jp < 3; jp++) {
                int r0 = ksel * 32 + nb * 4 + i;
                int c  = 144 + coff + 2 * jp;
                *(float2*)&smem[r0 * 192 + c] =
                    make_float2(acc[i * 6 + 2 * jp], acc[i * 6 + 2 * jp + 1]);
            }
    }
    __syncthreads();

    // ---- epilogue: Theta contraction + exact fp32 diagonal terms + ReLU ----
    float th0[FIN], th1[FIN], th2[FIN];
    #pragma unroll
    for (int f = 0; f < FIN; f++) {
        th0[f] = Theta[f * FOUT + o];
        th1[f] = Theta[(FIN + f) * FOUT + o];
        th2[f] = Theta[(2 * FIN + f) * FOUT + o];
    }
    const float* sa0 = sa + (size_t)(b * 3) * NDIM * NDIM;

    #pragma unroll 1
    for (int nn = 0; nn < 8; nn++) {
        int nl = ngrp * 8 + nn;
        int n  = n0 + nl;
        float adjd = adj[(size_t)n * NDIM + n];
        float Lnn  = g_deg[n] - adjd;
        float w0 = __expf(sa0[(size_t)n * NDIM + n]) * g_inv0[b * NDIM + n];
        float w1 = Lnn * __expf(sa1[(size_t)n * NDIM + n]) * inv1r[nn];
        float w2 = (2.f * Lnn * Lnn - 1.f) * __expf(sa2[(size_t)n * NDIM + n]) * inv2r[nn];

        float vals[TDIM];
        #pragma unroll
        for (int t = 0; t < TDIM; t++) vals[t] = 0.f;
        const float* xr = xb + (size_t)n * CDIM;

        #pragma unroll
        for (int f = 0; f < FIN; f++) {
            float a1f = th1[f] * inv1r[nn];
            float a2f = th2[f] * inv2r[nn];
            float wdf = w0 * th0[f] + w1 * th1[f] + w2 * th2[f];
            #pragma unroll
            for (int tq = 0; tq < 3; tq++) {
                float4 r1 = *(const float4*)&smem[nl * 192 + f * 12 + tq * 4];
                float4 r2 = *(const float4*)&smem[(32 + nl) * 192 + f * 12 + tq * 4];
                float4 xv = *(const float4*)&xr[f * 12 + tq * 4];
                vals[tq * 4 + 0] += r1.x * a1f + r2.x * a2f + xv.x * wdf;
                vals[tq * 4 + 1] += r1.y * a1f + r2.y * a2f + xv.y * wdf;
                vals[tq * 4 + 2] += r1.z * a1f + r2.z * a2f + xv.z * wdf;
                vals[tq * 4 + 3] += r1.w * a1f + r2.w * a2f + xv.w * wdf;
            }
        }
        float* op = out + (((size_t)b * NDIM + n) * FOUT + o) * TDIM;
        #pragma unroll
        for (int tq = 0; tq < 3; tq++) {
            float4 v;
            v.x = fmaxf(vals[tq * 4 + 0], 0.f);
            v.y = fmaxf(vals[tq * 4 + 1], 0.f);
            v.z = fmaxf(vals[tq * 4 + 2], 0.f);
            v.w = fmaxf(vals[tq * 4 + 3], 0.f);
            *(float4*)&op[tq * 4] = v;
        }
    }
}

// ---------------------------------------------------------------------------
extern "C" void kernel_launch(void* const* d_in, const int* in_sizes, int n_in,
                              void* d_out, int out_size) {
    const float* x     = (const float*)d_in[0];  // (B,N,FIN,T)
    const float* sa    = (const float*)d_in[1];  // (B,K,N,N)
    const float* adj   = (const float*)d_in[2];  // (N,N)
    const float* Theta = (const float*)d_in[3];  // (K,FIN,FOUT)
    float* out = (float*)d_out;                  // (B,N,FOUT,T)

    xT_kernel<<<dim3(NDIM / 32, CDIM / 32, BDIM), 256>>>(x);
    prep_kernel<<<dim3(8, 9), 256>>>(sa, adj);
    main_kernel<<<dim3(NDIM / TM, BDIM), 256>>>(x, sa, adj, Theta, out);
}

// round 10
// speedup vs baseline: 2.8240x; 2.8240x over previous
#include <cuda_runtime.h>
#include <cuda_bf16.h>
#include <cstdint>

#define BDIM 8
#define NDIM 2048
#define FIN 16
#define FOUT 64
#define TDIM 12
#define CDIM 192
#define TM 32            // n-tile per CTA
#define MC 32            // m per chunk
#define NCH (NDIM/MC)    // 64 chunks
#define ASTR 20          // packed A smem word stride (conflict-free frags)
#define XSTR 20          // packed X smem word stride
#define BUFW 5120        // words per ping-pong buffer: 640+640+3840

// ---- device scratch (no cudaMalloc allowed) ----
__device__ float g_deg[NDIM];
__device__ uint32_t g_xTb[(size_t)BDIM*CDIM*(NDIM/2)];  // bf16x2 (x[m],x[m+1]) at [b][c][m/2]

__device__ __forceinline__ uint32_t pack2(float a, float b) {
    __nv_bfloat162 h = __floats2bfloat162_rn(a, b);
    return *(uint32_t*)&h;
}

// ---------------------------------------------------------------------------
// x[b][m][c] (f32) -> g_xTb[b][c][m/2] (bf16x2)
__global__ void xT_kernel(const float* __restrict__ x) {
    __shared__ float t[32][33];
    int b = blockIdx.z, c0 = blockIdx.y * 32, m0 = blockIdx.x * 32;
    int tx = threadIdx.x & 31, ty = threadIdx.x >> 5;
    #pragma unroll
    for (int j = 0; j < 4; j++)
        t[ty + j * 8][tx] = x[((size_t)b * NDIM + m0 + ty + j * 8) * CDIM + c0 + tx];
    __syncthreads();
    int q = threadIdx.x & 15;
    int cbase = threadIdx.x >> 4;
    #pragma unroll
    for (int j = 0; j < 2; j++) {
        int cc = cbase + 16 * j;
        uint32_t v = pack2(t[2 * q][cc], t[2 * q + 1][cc]);
        g_xTb[(((size_t)b * CDIM + c0 + cc) << 10) + (m0 >> 1) + q] = v;
    }
}

// ---------------------------------------------------------------------------
// deg[i] = sum_j adj[i][j]  (warp per row)
__global__ void deg_kernel(const float* __restrict__ adj) {
    int row = (blockIdx.x * blockDim.x + threadIdx.x) >> 5;
    int lane = threadIdx.x & 31;
    if (row >= NDIM) return;
    const float4* r = (const float4*)(adj + (size_t)row * NDIM);
    float s = 0.f;
    #pragma unroll
    for (int i = 0; i < 16; i++) {
        float4 v = r[lane + i * 32];
        s += v.x + v.y + v.z + v.w;
    }
    #pragma unroll
    for (int o = 16; o; o >>= 1) s += __shfl_xor_sync(0xffffffffu, s, o);
    if (lane == 0) g_deg[row] = s;
}

// ---------------------------------------------------------------------------
// Fused main kernel: software-pipelined ping-pong buffers, 1 barrier/chunk.
// All 8 warps run bf16 m16n8k16 HMMA (k in {1,2} x 4 col-groups of 48).
// Softmax denominators for k=0,1,2 accumulated in the build pass; exact
// fp32 diagonal terms + Theta + ReLU in the epilogue.
__global__ __launch_bounds__(256, 2)
void main_kernel(const float* __restrict__ x,
                 const float* __restrict__ sa,
                 const float* __restrict__ adj,
                 const float* __restrict__ Theta,
                 float* __restrict__ out)
{
    __shared__ float smem[12288];          // 48 KB: 2 x BUFW mainloop, full overlay in epilogue

    const int b    = blockIdx.y;
    const int n0   = blockIdx.x * TM;
    const int tid  = threadIdx.x;
    const int lane = tid & 31;
    const int wid  = tid >> 5;
    const int g    = lane >> 2;
    const int tig  = lane & 3;
    const int ksel = wid & 1;              // 0 -> k=1, 1 -> k=2
    const int cg0  = (wid >> 1) * 48;      // 48-col group per warp pair

    const float* sa0 = sa + (size_t)(b * 3 + 0) * NDIM * NDIM;
    const float* sa1 = sa + (size_t)(b * 3 + 1) * NDIM * NDIM;
    const float* sa2 = sa + (size_t)(b * 3 + 2) * NDIM * NDIM;
    const float* xb  = x + (size_t)b * NDIM * CDIM;
    const uint32_t* xsrc = &g_xTb[((size_t)b * CDIM) << 10];
    const int n_g = n0 + lane;

    float acc[48];                         // [2 rt][6 ct][4]
    #pragma unroll
    for (int i = 0; i < 48; i++) acc[i] = 0.f;
    float sum0 = 0.f, sum1 = 0.f, sum2 = 0.f;

    // prefetch registers for next chunk
    float ra[4], r0v[4], r1v[4], r2v[4];
    uint32_t nx[12];

    auto PREFETCH = [&](int ch) {
        int mb = ch * MC;
        #pragma unroll
        for (int i = 0; i < 2; i++) {
            int m = mb + (wid * 2 + i) * 2;
            size_t o0 = (size_t)m * NDIM + n_g;
            ra[2*i]    = __ldg(&adj[o0]);
            ra[2*i+1]  = __ldg(&adj[o0 + NDIM]);
            r0v[2*i]   = __ldg(&sa0[o0]);
            r0v[2*i+1] = __ldg(&sa0[o0 + NDIM]);
            r1v[2*i]   = __ldg(&sa1[o0]);
            r1v[2*i+1] = __ldg(&sa1[o0 + NDIM]);
            r2v[2*i]   = __ldg(&sa2[o0]);
            r2v[2*i+1] = __ldg(&sa2[o0 + NDIM]);
        }
        #pragma unroll
        for (int i = 0; i < 12; i++) {
            int e = tid + i * 256;         // 0..3071
            int c = e >> 4, q = e & 15;
            nx[i] = __ldg(&xsrc[((size_t)c << 10) + (mb >> 1) + q]);
        }
    };

    auto STORE = [&](int ch, int p) {
        float* base = smem + p * BUFW;
        uint32_t* A1w = (uint32_t*)base;
        uint32_t* A2w = (uint32_t*)(base + 640);
        uint32_t* Xw  = (uint32_t*)(base + 1280);
        int mb = ch * MC;
        #pragma unroll
        for (int i = 0; i < 2; i++) {
            int pp = wid * 2 + i;          // m-pair 0..15
            int m = mb + 2 * pp;
            float e00 = __expf(r0v[2*i]), e01 = __expf(r0v[2*i+1]);
            float e10 = __expf(r1v[2*i]), e11 = __expf(r1v[2*i+1]);
            float e20 = __expf(r2v[2*i]), e21 = __expf(r2v[2*i+1]);
            sum0 += e00 + e01; sum1 += e10 + e11; sum2 += e20 + e21;
            bool d0 = (m == n_g), d1 = (m + 1 == n_g);
            float a0 = ra[2*i], a1 = ra[2*i+1];
            float w10 = d0 ? 0.f : (-a0) * e10;
            float w11 = d1 ? 0.f : (-a1) * e11;
            float w20 = d0 ? 0.f : (2.f * a0 * a0) * e20;
            float w21 = d1 ? 0.f : (2.f * a1 * a1) * e21;
            A1w[lane * ASTR + pp] = pack2(w10, w11);
            A2w[lane * ASTR + pp] = pack2(w20, w21);
        }
        #pragma unroll
        for (int i = 0; i < 12; i++) {
            int e = tid + i * 256;
            int c = e >> 4, q = e & 15;
            Xw[c * XSTR + q] = nx[i];
        }
    };

    auto MMA = [&](int p) {
        float* base = smem + p * BUFW;
        const uint32_t* A1w = (const uint32_t*)base;
        const uint32_t* A2w = (const uint32_t*)(base + 640);
        const uint32_t* Xw  = (const uint32_t*)(base + 1280);
        const uint32_t* Aw  = ksel ? A2w : A1w;
        #pragma unroll
        for (int kk = 0; kk < 2; kk++) {
            uint32_t afr[2][4];
            #pragma unroll
            for (int rt = 0; rt < 2; rt++) {
                int r0 = rt * 16 + g;
                afr[rt][0] = Aw[r0 * ASTR + kk * 8 + tig];
                afr[rt][1] = Aw[(r0 + 8) * ASTR + kk * 8 + tig];
                afr[rt][2] = Aw[r0 * ASTR + kk * 8 + tig + 4];
                afr[rt][3] = Aw[(r0 + 8) * ASTR + kk * 8 + tig + 4];
            }
            #pragma unroll
            for (int ct = 0; ct < 6; ct++) {
                int c = cg0 + ct * 8 + g;
                uint32_t b0 = Xw[c * XSTR + kk * 8 + tig];
                uint32_t b1 = Xw[c * XSTR + kk * 8 + tig + 4];
                #pragma unroll
                for (int rt = 0; rt < 2; rt++) {
                    float* dd = &acc[(rt * 6 + ct) * 4];
                    asm volatile(
                        "mma.sync.aligned.m16n8k16.row.col.f32.bf16.bf16.f32 "
                        "{%0,%1,%2,%3}, {%4,%5,%6,%7}, {%8,%9}, {%0,%1,%2,%3};\n"
                        : "+f"(dd[0]), "+f"(dd[1]), "+f"(dd[2]), "+f"(dd[3])
                        : "r"(afr[rt][0]), "r"(afr[rt][1]), "r"(afr[rt][2]), "r"(afr[rt][3]),
                          "r"(b0), "r"(b1));
                }
            }
        }
    };

    // ---- pipelined mainloop: 1 barrier per chunk ----
    PREFETCH(0);
    STORE(0, 0);
    __syncthreads();
    for (int ch = 0; ch < NCH; ch++) {
        int p = ch & 1;
        if (ch + 1 < NCH) PREFETCH(ch + 1);
        MMA(p);
        if (ch + 1 < NCH) STORE(ch + 1, p ^ 1);
        __syncthreads();
    }

    // ---- softmax denominators: reduce 8 partials per column, k=0,1,2 ----
    smem[wid * 32 + lane]       = sum0;
    smem[256 + wid * 32 + lane] = sum1;
    smem[512 + wid * 32 + lane] = sum2;
    __syncthreads();
    if (tid < 96) {
        int k = tid >> 5, nl = tid & 31;
        float s = 0.f;
        #pragma unroll
        for (int w = 0; w < 8; w++) s += smem[k * 256 + w * 32 + nl];
        smem[768 + k * 32 + nl] = 1.f / s;
    }
    __syncthreads();

    const int o    = tid & 63;
    const int ngrp = tid >> 6;
    float inv0r[8], inv1r[8], inv2r[8];
    #pragma unroll
    for (int nn = 0; nn < 8; nn++) {
        int nl = ngrp * 8 + nn;
        inv0r[nn] = smem[768 + nl];
        inv1r[nn] = smem[800 + nl];
        inv2r[nn] = smem[832 + nl];
    }
    __syncthreads();

    // ---- spill accumulators to rhs smem [k][32 n][192 c] ----
    #pragma unroll
    for (int rt = 0; rt < 2; rt++)
        #pragma unroll
        for (int ct = 0; ct < 6; ct++) {
            const float* dd = &acc[(rt * 6 + ct) * 4];
            int r0 = ksel * 32 + rt * 16 + g;
            int c  = cg0 + ct * 8 + 2 * tig;
            *(float2*)&smem[r0 * 192 + c]       = make_float2(dd[0], dd[1]);
            *(float2*)&smem[(r0 + 8) * 192 + c] = make_float2(dd[2], dd[3]);
        }
    __syncthreads();

    // ---- epilogue: Theta contraction + exact fp32 diagonal terms + ReLU ----
    float th0[FIN], th1[FIN], th2[FIN];
    #pragma unroll
    for (int f = 0; f < FIN; f++) {
        th0[f] = Theta[f * FOUT + o];
        th1[f] = Theta[(FIN + f) * FOUT + o];
        th2[f] = Theta[(2 * FIN + f) * FOUT + o];
    }

    #pragma unroll 1
    for (int nn = 0; nn < 8; nn++) {
        int nl = ngrp * 8 + nn;
        int n  = n0 + nl;
        float adjd = adj[(size_t)n * NDIM + n];
        float Lnn  = g_deg[n] - adjd;
        float w0 = __expf(sa0[(size_t)n * NDIM + n]) * inv0r[nn];
        float w1 = Lnn * __expf(sa1[(size_t)n * NDIM + n]) * inv1r[nn];
        float w2 = (2.f * Lnn * Lnn - 1.f) * __expf(sa2[(size_t)n * NDIM + n]) * inv2r[nn];

        float vals[TDIM];
        #pragma unroll
        for (int t = 0; t < TDIM; t++) vals[t] = 0.f;
        const float* xr = xb + (size_t)n * CDIM;

        #pragma unroll
        for (int f = 0; f < FIN; f++) {
            float a1f = th1[f] * inv1r[nn];
            float a2f = th2[f] * inv2r[nn];
            float wdf = w0 * th0[f] + w1 * th1[f] + w2 * th2[f];
            #pragma unroll
            for (int tq = 0; tq < 3; tq++) {
                float4 r1 = *(const float4*)&smem[nl * 192 + f * 12 + tq * 4];
                float4 r2 = *(const float4*)&smem[(32 + nl) * 192 + f * 12 + tq * 4];
                float4 xv = *(const float4*)&xr[f * 12 + tq * 4];
                vals[tq * 4 + 0] += r1.x * a1f + r2.x * a2f + xv.x * wdf;
                vals[tq * 4 + 1] += r1.y * a1f + r2.y * a2f + xv.y * wdf;
                vals[tq * 4 + 2] += r1.z * a1f + r2.z * a2f + xv.z * wdf;
                vals[tq * 4 + 3] += r1.w * a1f + r2.w * a2f + xv.w * wdf;
            }
        }
        float* op = out + (((size_t)b * NDIM + n) * FOUT + o) * TDIM;
        #pragma unroll
        for (int tq = 0; tq < 3; tq++) {
            float4 v;
            v.x = fmaxf(vals[tq * 4 + 0], 0.f);
            v.y = fmaxf(vals[tq * 4 + 1], 0.f);
            v.z = fmaxf(vals[tq * 4 + 2], 0.f);
            v.w = fmaxf(vals[tq * 4 + 3], 0.f);
            *(float4*)&op[tq * 4] = v;
        }
    }
}

// ---------------------------------------------------------------------------
extern "C" void kernel_launch(void* const* d_in, const int* in_sizes, int n_in,
                              void* d_out, int out_size) {
    const float* x     = (const float*)d_in[0];  // (B,N,FIN,T)
    const float* sa    = (const float*)d_in[1];  // (B,K,N,N)
    const float* adj   = (const float*)d_in[2];  // (N,N)
    const float* Theta = (const float*)d_in[3];  // (K,FIN,FOUT)
    float* out = (float*)d_out;                  // (B,N,FOUT,T)

    xT_kernel<<<dim3(NDIM / 32, CDIM / 32, BDIM), 256>>>(x);
    deg_kernel<<<NDIM * 32 / 256, 256>>>(adj);
    main_kernel<<<dim3(NDIM / TM, BDIM), 256>>>(x, sa, adj, Theta, out);
}

// round 12
// speedup vs baseline: 3.0296x; 1.0728x over previous
#include <cuda_runtime.h>
#include <cuda_bf16.h>
#include <cstdint>

#define BDIM 8
#define NDIM 2048
#define FIN 16
#define FOUT 64
#define TDIM 12
#define CDIM 192
#define TM 32            // n-tile per CTA
#define MC 32            // m per chunk (= K of one fp8 MMA)
#define NCH (NDIM/MC)    // 64 chunks
#define AST 9            // A smem word stride ([32 n][8 quads] + pad)
#define XST 9            // X smem word stride ([192 c][8 quads] + pad)
#define ABUF 288         // words per A tile (32*9)
#define BUFW 2304        // words per ping-pong buffer: 288+288+1728

// ---- device scratch (no cudaMalloc allowed) ----
__device__ float g_deg[NDIM];
__device__ uint32_t g_xTq[(size_t)BDIM*CDIM*(NDIM/4)];  // e4m3 quads: x[b, m..m+3, c] at [b][c][m/4]

// pack 4 floats -> 4 e4m3 bytes (byte0 = a)
__device__ __forceinline__ uint32_t pack4_e4m3(float a, float b, float c, float d) {
    uint16_t lo, hi;
    asm("cvt.rn.satfinite.e4m3x2.f32 %0, %1, %2;" : "=h"(lo) : "f"(b), "f"(a));
    asm("cvt.rn.satfinite.e4m3x2.f32 %0, %1, %2;" : "=h"(hi) : "f"(d), "f"(c));
    return (uint32_t)lo | ((uint32_t)hi << 16);
}

// ---------------------------------------------------------------------------
// x[b][m][c] (f32) -> g_xTq[b][c][m/4] (e4m3 x4)
__global__ void xT_kernel(const float* __restrict__ x) {
    __shared__ float t[32][33];
    int b = blockIdx.z, c0 = blockIdx.y * 32, m0 = blockIdx.x * 32;
    int tx = threadIdx.x & 31, ty = threadIdx.x >> 5;
    #pragma unroll
    for (int j = 0; j < 4; j++)
        t[ty + j * 8][tx] = x[((size_t)b * NDIM + m0 + ty + j * 8) * CDIM + c0 + tx];
    __syncthreads();
    int q  = threadIdx.x & 7;        // m-quad 0..7
    int cc = threadIdx.x >> 3;       // 0..31
    uint32_t v = pack4_e4m3(t[4 * q][cc], t[4 * q + 1][cc], t[4 * q + 2][cc], t[4 * q + 3][cc]);
    g_xTq[(((size_t)b * CDIM + c0 + cc) << 9) + (m0 >> 2) + q] = v;
}

// ---------------------------------------------------------------------------
// deg[i] = sum_j adj[i][j]  (warp per row)
__global__ void deg_kernel(const float* __restrict__ adj) {
    int row = (blockIdx.x * blockDim.x + threadIdx.x) >> 5;
    int lane = threadIdx.x & 31;
    if (row >= NDIM) return;
    const float4* r = (const float4*)(adj + (size_t)row * NDIM);
    float s = 0.f;
    #pragma unroll
    for (int i = 0; i < 16; i++) {
        float4 v = r[lane + i * 32];
        s += v.x + v.y + v.z + v.w;
    }
    #pragma unroll
    for (int o = 16; o; o >>= 1) s += __shfl_xor_sync(0xffffffffu, s, o);
    if (lane == 0) g_deg[row] = s;
}

// ---------------------------------------------------------------------------
// Fused main kernel: fp8 e4m3 m16n8k32 MMA, ping-pong pipeline, 1 barrier/chunk.
// Off-diagonal weights quantized to e4m3 (satfinite); the dominant diagonal
// terms + softmax normalization stay exact fp32 in the epilogue.
__global__ __launch_bounds__(256, 2)
void main_kernel(const float* __restrict__ x,
                 const float* __restrict__ sa,
                 const float* __restrict__ adj,
                 const float* __restrict__ Theta,
                 float* __restrict__ out)
{
    __shared__ float smem[12288];          // 48 KB: 2 x BUFW mainloop (4608 w), full overlay later

    const int b    = blockIdx.y;
    const int n0   = blockIdx.x * TM;
    const int tid  = threadIdx.x;
    const int lane = tid & 31;
    const int wid  = tid >> 5;
    const int g    = lane >> 2;
    const int tig  = lane & 3;
    const int ksel = wid & 1;              // 0 -> k=1, 1 -> k=2
    const int cg0  = (wid >> 1) * 48;      // 48-col group per warp pair

    const float* sa0 = sa + (size_t)(b * 3 + 0) * NDIM * NDIM;
    const float* sa1 = sa + (size_t)(b * 3 + 1) * NDIM * NDIM;
    const float* sa2 = sa + (size_t)(b * 3 + 2) * NDIM * NDIM;
    const float* xb  = x + (size_t)b * NDIM * CDIM;
    const uint32_t* xsrc = &g_xTq[((size_t)b * CDIM) << 9];
    const int n_g = n0 + lane;

    float acc[48];                         // [2 rt][6 ct][4]
    #pragma unroll
    for (int i = 0; i < 48; i++) acc[i] = 0.f;
    float sum0 = 0.f, sum1 = 0.f, sum2 = 0.f;

    // prefetch registers for next chunk: this thread's 4 consecutive m's
    float ra[4], r0v[4], r1v[4], r2v[4];
    uint32_t nx[6];

    auto PREFETCH = [&](int ch) {
        int m = ch * MC + wid * 4;
        size_t o0 = (size_t)m * NDIM + n_g;
        #pragma unroll
        for (int i = 0; i < 4; i++) {
            ra[i]  = __ldg(&adj[o0 + (size_t)i * NDIM]);
            r0v[i] = __ldg(&sa0[o0 + (size_t)i * NDIM]);
            r1v[i] = __ldg(&sa1[o0 + (size_t)i * NDIM]);
            r2v[i] = __ldg(&sa2[o0 + (size_t)i * NDIM]);
        }
        #pragma unroll
        for (int i = 0; i < 6; i++) {
            int e = tid + i * 256;         // 0..1535
            int c = e >> 3, q = e & 7;
            nx[i] = __ldg(&xsrc[((size_t)c << 9) + (ch * MC >> 2) + q]);
        }
    };

    auto STORE = [&](int ch, int p) {
        float* base = smem + p * BUFW;
        uint32_t* A1w = (uint32_t*)base;
        uint32_t* A2w = (uint32_t*)(base + ABUF);
        uint32_t* Xw  = (uint32_t*)(base + 2 * ABUF);
        int mb = ch * MC + wid * 4;
        float w1v[4], w2v[4];
        #pragma unroll
        for (int i = 0; i < 4; i++) {
            float e0 = __expf(r0v[i]);
            float e1 = __expf(r1v[i]);
            float e2 = __expf(r2v[i]);
            sum0 += e0; sum1 += e1; sum2 += e2;
            bool dg = (mb + i == n_g);
            w1v[i] = dg ? 0.f : (-ra[i]) * e1;
            w2v[i] = dg ? 0.f : (2.f * ra[i] * ra[i]) * e2;
        }
        A1w[lane * AST + wid] = pack4_e4m3(w1v[0], w1v[1], w1v[2], w1v[3]);
        A2w[lane * AST + wid] = pack4_e4m3(w2v[0], w2v[1], w2v[2], w2v[3]);
        #pragma unroll
        for (int i = 0; i < 6; i++) {
            int e = tid + i * 256;
            int c = e >> 3, q = e & 7;
            Xw[c * XST + q] = nx[i];
        }
    };

    auto MMA = [&](int p) {
        float* base = smem + p * BUFW;
        const uint32_t* Aw = (const uint32_t*)(base + (ksel ? ABUF : 0));
        const uint32_t* Xw = (const uint32_t*)(base + 2 * ABUF);
        uint32_t afr[2][4];
        #pragma unroll
        for (int rt = 0; rt < 2; rt++) {
            int r0 = rt * 16 + g;
            afr[rt][0] = Aw[r0 * AST + tig];
            afr[rt][1] = Aw[(r0 + 8) * AST + tig];
            afr[rt][2] = Aw[r0 * AST + tig + 4];
            afr[rt][3] = Aw[(r0 + 8) * AST + tig + 4];
        }
        #pragma unroll
        for (int ct = 0; ct < 6; ct++) {
            int c = cg0 + ct * 8 + g;
            uint32_t b0 = Xw[c * XST + tig];
            uint32_t b1 = Xw[c * XST + tig + 4];
            #pragma unroll
            for (int rt = 0; rt < 2; rt++) {
                float* dd = &acc[(rt * 6 + ct) * 4];
                asm volatile(
                    "mma.sync.aligned.m16n8k32.row.col.f32.e4m3.e4m3.f32 "
                    "{%0,%1,%2,%3}, {%4,%5,%6,%7}, {%8,%9}, {%0,%1,%2,%3};\n"
                    : "+f"(dd[0]), "+f"(dd[1]), "+f"(dd[2]), "+f"(dd[3])
                    : "r"(afr[rt][0]), "r"(afr[rt][1]), "r"(afr[rt][2]), "r"(afr[rt][3]),
                      "r"(b0), "r"(b1));
            }
        }
    };

    // ---- pipelined mainloop: 1 barrier per chunk ----
    PREFETCH(0);
    STORE(0, 0);
    __syncthreads();
    for (int ch = 0; ch < NCH; ch++) {
        int p = ch & 1;
        if (ch + 1 < NCH) PREFETCH(ch + 1);
        MMA(p);
        if (ch + 1 < NCH) STORE(ch + 1, p ^ 1);
        __syncthreads();
    }

    // ---- softmax denominators: reduce 8 partials per column, k=0,1,2 ----
    smem[wid * 32 + lane]       = sum0;
    smem[256 + wid * 32 + lane] = sum1;
    smem[512 + wid * 32 + lane] = sum2;
    __syncthreads();
    if (tid < 96) {
        int k = tid >> 5, nl = tid & 31;
        float s = 0.f;
        #pragma unroll
        for (int w = 0; w < 8; w++) s += smem[k * 256 + w * 32 + nl];
        smem[768 + k * 32 + nl] = 1.f / s;
    }
    __syncthreads();

    const int o    = tid & 63;
    const int ngrp = tid >> 6;
    float inv0r[8], inv1r[8], inv2r[8];
    #pragma unroll
    for (int nn = 0; nn < 8; nn++) {
        int nl = ngrp * 8 + nn;
        inv0r[nn] = smem[768 + nl];
        inv1r[nn] = smem[800 + nl];
        inv2r[nn] = smem[832 + nl];
    }
    __syncthreads();

    // ---- spill accumulators to rhs smem [k][32 n][192 c] ----
    #pragma unroll
    for (int rt = 0; rt < 2; rt++)
        #pragma unroll
        for (int ct = 0; ct < 6; ct++) {
            const float* dd = &acc[(rt * 6 + ct) * 4];
            int r0 = ksel * 32 + rt * 16 + g;
            int c  = cg0 + ct * 8 + 2 * tig;
            *(float2*)&smem[r0 * 192 + c]       = make_float2(dd[0], dd[1]);
            *(float2*)&smem[(r0 + 8) * 192 + c] = make_float2(dd[2], dd[3]);
        }
    __syncthreads();

    // ---- epilogue: Theta contraction + exact fp32 diagonal terms + ReLU ----
    float th0[FIN], th1[FIN], th2[FIN];
    #pragma unroll
    for (int f = 0; f < FIN; f++) {
        th0[f] = Theta[f * FOUT + o];
        th1[f] = Theta[(FIN + f) * FOUT + o];
        th2[f] = Theta[(2 * FIN + f) * FOUT + o];
    }

    #pragma unroll 1
    for (int nn = 0; nn < 8; nn++) {
        int nl = ngrp * 8 + nn;
        int n  = n0 + nl;
        float adjd = adj[(size_t)n * NDIM + n];
        float Lnn  = g_deg[n] - adjd;
        float w0 = __expf(sa0[(size_t)n * NDIM + n]) * inv0r[nn];
        float w1 = Lnn * __expf(sa1[(size_t)n * NDIM + n]) * inv1r[nn];
        float w2 = (2.f * Lnn * Lnn - 1.f) * __expf(sa2[(size_t)n * NDIM + n]) * inv2r[nn];

        float vals[TDIM];
        #pragma unroll
        for (int t = 0; t < TDIM; t++) vals[t] = 0.f;
        const float* xr = xb + (size_t)n * CDIM;

        #pragma unroll
        for (int f = 0; f < FIN; f++) {
            float a1f = th1[f] * inv1r[nn];
            float a2f = th2[f] * inv2r[nn];
            float wdf = w0 * th0[f] + w1 * th1[f] + w2 * th2[f];
            #pragma unroll
            for (int tq = 0; tq < 3; tq++) {
                float4 r1 = *(const float4*)&smem[nl * 192 + f * 12 + tq * 4];
                float4 r2 = *(const float4*)&smem[(32 + nl) * 192 + f * 12 + tq * 4];
                float4 xv = *(const float4*)&xr[f * 12 + tq * 4];
                vals[tq * 4 + 0] += r1.x * a1f + r2.x * a2f + xv.x * wdf;
                vals[tq * 4 + 1] += r1.y * a1f + r2.y * a2f + xv.y * wdf;
                vals[tq * 4 + 2] += r1.z * a1f + r2.z * a2f + xv.z * wdf;
                vals[tq * 4 + 3] += r1.w * a1f + r2.w * a2f + xv.w * wdf;
            }
        }
        float* op = out + (((size_t)b * NDIM + n) * FOUT + o) * TDIM;
        #pragma unroll
        for (int tq = 0; tq < 3; tq++) {
            float4 v;
            v.x = fmaxf(vals[tq * 4 + 0], 0.f);
            v.y = fmaxf(vals[tq * 4 + 1], 0.f);
            v.z = fmaxf(vals[tq * 4 + 2], 0.f);
            v.w = fmaxf(vals[tq * 4 + 3], 0.f);
            *(float4*)&op[tq * 4] = v;
        }
    }
}

// ---------------------------------------------------------------------------
extern "C" void kernel_launch(void* const* d_in, const int* in_sizes, int n_in,
                              void* d_out, int out_size) {
    const float* x     = (const float*)d_in[0];  // (B,N,FIN,T)
    const float* sa    = (const float*)d_in[1];  // (B,K,N,N)
    const float* adj   = (const float*)d_in[2];  // (N,N)
    const float* Theta = (const float*)d_in[3];  // (K,FIN,FOUT)
    float* out = (float*)d_out;                  // (B,N,FOUT,T)

    xT_kernel<<<dim3(NDIM / 32, CDIM / 32, BDIM), 256>>>(x);
    deg_kernel<<<NDIM * 32 / 256, 256>>>(adj);
    main_kernel<<<dim3(NDIM / TM, BDIM), 256>>>(x, sa, adj, Theta, out);
}